// round 15
// baseline (speedup 1.0000x reference)
#include <cuda_runtime.h>
#include <cuda_fp16.h>
#include <cstdint>

// ---------------- problem constants ----------------
#define S_LEN 2048
#define BATCH 16
#define DIM   1024
#define M_TOT (S_LEN*BATCH)      // 32768
#define N_TOT (3*DIM)            // 3072
#define K_TOT DIM                // 1024

// GEMM tiling (fp16 operands, fp32 accum) — 2 CTAs/SM, BK=64 (R10 plateau config)
#define BM 128
#define BN 128
#define BK 64
#define KSTEPS (K_TOT/BK)        // 16
#define NSTAGE 3
#define LOOKAHEAD 2
#define THREADS 256
#define SA_BYTES (BM*BK*2)       // 16384 per stage
#define SB_BYTES (BN*BK*2)       // 16384 per stage
#define SMEM_TOTAL (NSTAGE*(SA_BYTES+SB_BYTES))   // 98304 per CTA

// scan partitioning
#define SEGS 64
#define SEGLEN (S_LEN/SEGS)      // 32
#define CH (BATCH*DIM)           // 16384
#define CH2 (CH/2)               // 8192 channel-pairs

// conversion sizes (in float4 units)
#define X4 (M_TOT*K_TOT/4)       // 8388608
#define W4 (N_TOT*K_TOT/4)       // 786432
#define XCHUNK4 (X4/4)           // 2097152 float4 per m-chunk
#define MCHUNK (M_TOT/4)         // 8192 rows per chunk

// ---------------- device scratch ----------------
__device__ __half g_yact[(size_t)M_TOT * N_TOT]; // activated gates (fp16): tanh(Z), sig(F), sig(O)
__device__ __half g_Xh[(size_t)M_TOT * K_TOT];   // fp16-rounded X
__device__ __half g_Wh[(size_t)N_TOT * K_TOT];   // fp16-rounded W
__device__ float g_seg_a[SEGS*CH];
__device__ float g_seg_c[SEGS*CH];
__device__ float g_seg_s[SEGS*CH];

// ---------------- helpers ----------------
__device__ __forceinline__ uint32_t smem_u32(const void* p) {
    uint32_t a;
    asm("{ .reg .u64 t; cvta.to.shared.u64 t, %1; cvt.u32.u64 %0, t; }" : "=r"(a) : "l"(p));
    return a;
}
__device__ __forceinline__ void cp_async16(uint32_t dst, const void* src) {
    asm volatile("cp.async.cg.shared.global [%0], [%1], 16;" :: "r"(dst), "l"(src) : "memory");
}
__device__ __forceinline__ void cp_commit() {
    asm volatile("cp.async.commit_group;" ::: "memory");
}
__device__ __forceinline__ void cp_wait1() {
    asm volatile("cp.async.wait_group 1;" ::: "memory");
}

__device__ __forceinline__ void ldsm_x4(uint32_t* r, uint32_t addr) {
    asm volatile("ldmatrix.sync.aligned.m8n8.x4.shared.b16 {%0,%1,%2,%3}, [%4];"
        : "=r"(r[0]), "=r"(r[1]), "=r"(r[2]), "=r"(r[3]) : "r"(addr));
}

// mma.sync m16n8k16 fp16 in / fp32 accumulate (baseline PTX, sm_80+)
__device__ __forceinline__ void mma_f16(float* d, const uint32_t* a, uint32_t b0, uint32_t b1) {
    asm volatile(
        "mma.sync.aligned.m16n8k16.row.col.f32.f16.f16.f32 "
        "{%0,%1,%2,%3}, {%4,%5,%6,%7}, {%8,%9}, {%0,%1,%2,%3};"
        : "+f"(d[0]), "+f"(d[1]), "+f"(d[2]), "+f"(d[3])
        : "r"(a[0]), "r"(a[1]), "r"(a[2]), "r"(a[3]), "r"(b0), "r"(b1));
}

__device__ __forceinline__ float fsigmoid(float x) { return 1.0f / (1.0f + __expf(-x)); }
__device__ __forceinline__ float ftanh(float x)    { return 2.0f * fsigmoid(2.0f * x) - 1.0f; }

// streaming (evict-first) loads/stores
__device__ __forceinline__ uint32_t ldcs_u32(const uint32_t* p) {
    uint32_t v;
    asm volatile("ld.global.cs.b32 %0, [%1];" : "=r"(v) : "l"(p));
    return v;
}
__device__ __forceinline__ void stcs_f2(float* p, float2 v) {
    asm volatile("st.global.cs.v2.f32 [%0], {%1, %2};" :: "l"(p), "f"(v.x), "f"(v.y));
}

// smem swizzle for 128B rows (8 x 16B chunks): chunk ^= row&7
__device__ __forceinline__ uint32_t swz_addr(uint32_t base, int row, int chunk) {
    return base + row * 128 + (((uint32_t)(chunk ^ (row & 7))) << 4);
}

// ============================================================
// Kernel 0: fp32 -> fp16 conversion (chunked; float4 in, half4 out)
// ============================================================
__global__ void __launch_bounds__(256)
to_half_chunk(const float* __restrict__ src, __half* __restrict__ dst, int n4) {
    int i = blockIdx.x * 256 + threadIdx.x;
    if (i >= n4) return;
    float4 v = ((const float4*)src)[i];
    __half2 h0 = __float22half2_rn(make_float2(v.x, v.y));
    __half2 h1 = __float22half2_rn(make_float2(v.z, v.w));
    ((uint2*)dst)[i] = make_uint2(*(uint32_t*)&h0, *(uint32_t*)&h1);
}

// ============================================================
// Kernel 1: Y = act(X @ W^T + b)  via mma.sync fp16 (n_base/m_base select range)
//   256 threads (8 warps = 4m x 2n of 32x64 tiles), 2 CTAs/SM
// ============================================================
__global__ void __launch_bounds__(THREADS, 2)
gemm_gates(const float* __restrict__ bias, int n_base, int m_base) {
    extern __shared__ char smem[];
    const uint32_t sA0 = smem_u32(smem);                    // 3 stages of A
    const uint32_t sB0 = sA0 + NSTAGE * SA_BYTES;           // 3 stages of B

    const int tid  = threadIdx.x;
    const int lane = tid & 31;
    const int wid  = tid >> 5;          // 0..7
    const int wm   = wid & 3;           // 32-row slice
    const int wn   = wid >> 2;          // 64-col slice (0..1)
    const int m0   = m_base + blockIdx.y * BM;
    const int nt   = n_base / BN + blockIdx.x;
    const int n0   = nt * BN;
    const int gate = nt >> 3;           // 0=Z(tanh) 1=F(sig) 2=O(sig)

    float acc[2][8][4];
    #pragma unroll
    for (int i = 0; i < 2; i++)
        #pragma unroll
        for (int j = 0; j < 8; j++)
            #pragma unroll
            for (int c = 0; c < 4; c++) acc[i][j][c] = 0.0f;

    // ---- cp.async fill (16B chunks; 8 per 128B row). A: 4/thr, B: 4/thr ----
    auto issue = [&](int kt, int buf) {
        const uint32_t sA = sA0 + buf * SA_BYTES;
        const uint32_t sB = sB0 + buf * SB_BYTES;
        const __half* xb = g_Xh + (size_t)m0 * K_TOT + kt * BK;
        const __half* wb = g_Wh + (size_t)n0 * K_TOT + kt * BK;
        #pragma unroll
        for (int i = 0; i < 4; i++) {
            int id = tid + i * THREADS;
            int r = id >> 3, c = id & 7;
            cp_async16(swz_addr(sA, r, c), xb + (size_t)r * K_TOT + c * 8);
        }
        #pragma unroll
        for (int i = 0; i < 4; i++) {
            int id = tid + i * THREADS;
            int r = id >> 3, c = id & 7;
            cp_async16(swz_addr(sB, r, c), wb + (size_t)r * K_TOT + c * 8);
        }
        cp_commit();
    };

    // ---- per-lane fragment addressing ----
    const int l15 = lane & 15;
    const int lhi = lane >> 4;                 // 0/1 -> k-lo / k-hi 16B chunk of k16 step
    const int aRowBase = wm * 32 + l15;        // + i*16
    const int bRowBase = wn * 64 + l15;        // + jb*16

    issue(0, 0);
    issue(1, 1);

    // fragment double buffers: a 2x2x4, b 2x4x4  (48 regs)
    uint32_t afr[2][2][4], bfr[2][4][4];

    for (int kt = 0; kt < KSTEPS; kt++) {
        cp_wait1();                              // group kt complete
        __syncthreads();                         // also WAR-protects issue below
        const int nb = kt + LOOKAHEAD;
        if (nb < KSTEPS) issue(nb, nb % NSTAGE);
        else             cp_commit();            // keep group count consistent

        const int buf = kt % NSTAGE;
        const uint32_t sA = sA0 + buf * SA_BYTES;
        const uint32_t sB = sB0 + buf * SB_BYTES;

        // prologue: load fragments of ks=0 into buffer 0
        {
            const int chunk = lhi;
            #pragma unroll
            for (int i = 0; i < 2; i++)
                ldsm_x4(afr[0][i], swz_addr(sA, aRowBase + i * 16, chunk));
            #pragma unroll
            for (int jb = 0; jb < 4; jb++)
                ldsm_x4(bfr[0][jb], swz_addr(sB, bRowBase + jb * 16, chunk));
        }

        #pragma unroll
        for (int ks = 0; ks < 4; ks++) {         // four k16 steps per BK=64
            const int cur = ks & 1, nxt = cur ^ 1;
            if (ks < 3) {                        // prefetch ks+1 fragments
                const int chunk = (ks + 1) * 2 + lhi;
                #pragma unroll
                for (int i = 0; i < 2; i++)
                    ldsm_x4(afr[nxt][i], swz_addr(sA, aRowBase + i * 16, chunk));
                #pragma unroll
                for (int jb = 0; jb < 4; jb++)
                    ldsm_x4(bfr[nxt][jb], swz_addr(sB, bRowBase + jb * 16, chunk));
            }
            #pragma unroll
            for (int jb = 0; jb < 4; jb++) {
                #pragma unroll
                for (int i = 0; i < 2; i++) {
                    mma_f16(acc[i][jb * 2 + 0], afr[cur][i], bfr[cur][jb][0], bfr[cur][jb][2]);
                    mma_f16(acc[i][jb * 2 + 1], afr[cur][i], bfr[cur][jb][1], bfr[cur][jb][3]);
                }
            }
        }
        // no trailing barrier: next iteration's wait+sync covers buffer reuse
    }

    // ---- epilogue: bias + activation, fp16 (half2) stores ----
    const int lrow = lane >> 2, lcol = lane & 3;
    #pragma unroll
    for (int j = 0; j < 8; j++) {
        const int n = n0 + wn * 64 + j * 8 + lcol * 2;   // even
        const float b0 = __ldg(bias + n);
        const float b1 = __ldg(bias + n + 1);
        #pragma unroll
        for (int i = 0; i < 2; i++) {
            const int m = m0 + wm * 32 + i * 16 + lrow;
            float y0 = acc[i][j][0] + b0, y1 = acc[i][j][1] + b1;
            float y2 = acc[i][j][2] + b0, y3 = acc[i][j][3] + b1;
            float2 v0, v1;
            if (gate == 0) {
                v0 = make_float2(ftanh(y0), ftanh(y1));
                v1 = make_float2(ftanh(y2), ftanh(y3));
            } else {
                v0 = make_float2(fsigmoid(y0), fsigmoid(y1));
                v1 = make_float2(fsigmoid(y2), fsigmoid(y3));
            }
            *(__half2*)&g_yact[(size_t)m * N_TOT + n]       = __float22half2_rn(v0);
            *(__half2*)&g_yact[(size_t)(m + 8) * N_TOT + n] = __float22half2_rn(v1);
        }
    }
}

// ============================================================
// Kernel 2: per-segment affine reduction, 2 channels/thread (streaming half2 loads)
//   a = prod(1-f), c = local scan from 0   (needs Z,F gates only)
// ============================================================
__global__ void __launch_bounds__(128)
scan_partial() {
    const int g = blockIdx.x * 128 + threadIdx.x;       // seg*CH2 + ch2
    const int seg = g >> 13;                            // /CH2
    const int ch2 = g & (CH2 - 1);
    const int b = ch2 >> 9, d2 = ch2 & 511;
    const uint32_t* Y = (const uint32_t*)g_yact;        // half2 row length N_TOT/2

    float2 a = make_float2(1.0f, 1.0f);
    float2 c = make_float2(0.0f, 0.0f);
    const int t0 = seg * SEGLEN;
    #pragma unroll 4
    for (int t = t0; t < t0 + SEGLEN; t++) {
        size_t rb = (size_t)(t * BATCH + b) * (N_TOT / 2);
        uint32_t zu = ldcs_u32(Y + rb + d2);
        uint32_t fu = ldcs_u32(Y + rb + (DIM / 2) + d2);
        float2 z = __half22float2(*(__half2*)&zu);
        float2 f = __half22float2(*(__half2*)&fu);
        c.x = fmaf(f.x, z.x - c.x, c.x);
        c.y = fmaf(f.y, z.y - c.y, c.y);
        a.x *= (1.0f - f.x);
        a.y *= (1.0f - f.y);
    }
    *(float2*)&g_seg_a[seg * CH + ch2 * 2] = a;
    *(float2*)&g_seg_c[seg * CH + ch2 * 2] = c;
}

// ============================================================
// Kernel 3: sequential combine over 64 segments; emits segment start states + C_last
// ============================================================
__global__ void __launch_bounds__(128)
scan_combine(const float* __restrict__ hidden, float* __restrict__ c_last) {
    const int ch2 = blockIdx.x * 128 + threadIdx.x;     // 0..CH2
    float2 s = *(const float2*)&hidden[ch2 * 2];
    // prefetch segment 0
    float2 aa = *(const float2*)&g_seg_a[ch2 * 2];
    float2 cc = *(const float2*)&g_seg_c[ch2 * 2];
    #pragma unroll
    for (int p = 0; p < SEGS; p++) {
        *(float2*)&g_seg_s[p * CH + ch2 * 2] = s;
        float2 na, nc;
        if (p + 1 < SEGS) {
            na = *(const float2*)&g_seg_a[(p + 1) * CH + ch2 * 2];
            nc = *(const float2*)&g_seg_c[(p + 1) * CH + ch2 * 2];
        }
        s.x = fmaf(aa.x, s.x, cc.x);
        s.y = fmaf(aa.y, s.y, cc.y);
        aa = na; cc = nc;
    }
    *(float2*)&c_last[ch2 * 2] = s;
}

// ============================================================
// Kernel 4: replay segments from start state, write H = sig(O) * C (streaming)
// ============================================================
__global__ void __launch_bounds__(128)
scan_final(float* __restrict__ H) {
    const int g = blockIdx.x * 128 + threadIdx.x;
    const int seg = g >> 13;
    const int ch2 = g & (CH2 - 1);
    const int b = ch2 >> 9, d2 = ch2 & 511;
    const uint32_t* Y = (const uint32_t*)g_yact;

    float2 h = *(const float2*)&g_seg_s[seg * CH + ch2 * 2];
    const int t0 = seg * SEGLEN;
    #pragma unroll 4
    for (int t = t0; t < t0 + SEGLEN; t++) {
        size_t rb = (size_t)(t * BATCH + b) * (N_TOT / 2);
        uint32_t zu = ldcs_u32(Y + rb + d2);
        uint32_t fu = ldcs_u32(Y + rb + (DIM / 2) + d2);
        uint32_t ou = ldcs_u32(Y + rb + DIM + d2);
        float2 z = __half22float2(*(__half2*)&zu);
        float2 f = __half22float2(*(__half2*)&fu);
        float2 o = __half22float2(*(__half2*)&ou);
        h.x = fmaf(f.x, z.x - h.x, h.x);
        h.y = fmaf(f.y, z.y - h.y, h.y);
        stcs_f2(&H[(size_t)(t * BATCH + b) * DIM + d2 * 2],
                make_float2(o.x * h.x, o.y * h.y));
    }
}

// ============================================================
// launcher — capture-legal fork/join:
//   s2 forks FROM stream 0 (wait on fork event), converts W + X chunks;
//   stream 0 runs gemmZF chunks gated on conversion events, then gemmO;
//   s2 runs scans overlapping gemmO; stream 0 joins for scan_final.
// ============================================================
extern "C" void kernel_launch(void* const* d_in, const int* in_sizes, int n_in,
                              void* d_out, int out_size) {
    const float* X      = (const float*)d_in[0];   // (S,B,D)
    const float* hidden = (const float*)d_in[1];   // (B,D)
    const float* W      = (const float*)d_in[2];   // (3D,D)
    const float* b      = (const float*)d_in[3];   // (3D,)
    float* out = (float*)d_out;                    // H (S,B,D) then C_last (1,B,D)

    static cudaStream_t s2 = nullptr;
    static cudaEvent_t evFork = nullptr;
    static cudaEvent_t cEv[4] = {nullptr, nullptr, nullptr, nullptr};
    static cudaEvent_t evZF = nullptr, evScan = nullptr;
    if (!s2) {
        cudaStreamCreateWithFlags(&s2, cudaStreamNonBlocking);
        cudaEventCreateWithFlags(&evFork, cudaEventDisableTiming);
        for (int i = 0; i < 4; i++) cudaEventCreateWithFlags(&cEv[i], cudaEventDisableTiming);
        cudaEventCreateWithFlags(&evZF, cudaEventDisableTiming);
        cudaEventCreateWithFlags(&evScan, cudaEventDisableTiming);
        cudaFuncSetAttribute(gemm_gates, cudaFuncAttributeMaxDynamicSharedMemorySize, SMEM_TOTAL);
    }

    __half* xh; cudaGetSymbolAddress((void**)&xh, g_Xh);
    __half* wh; cudaGetSymbolAddress((void**)&wh, g_Wh);

    // fork s2 from the capture-origin stream (required for graph capture)
    cudaEventRecord(evFork, 0);
    cudaStreamWaitEvent(s2, evFork, 0);

    // s2: convert W, then X in 4 m-chunks; event after each chunk
    to_half_chunk<<<(W4 + 255) / 256, 256, 0, s2>>>(W, wh, W4);
    for (int ch = 0; ch < 4; ch++) {
        to_half_chunk<<<(XCHUNK4 + 255) / 256, 256, 0, s2>>>(
            X + (size_t)ch * XCHUNK4 * 4, xh + (size_t)ch * XCHUNK4 * 4, XCHUNK4);
        cudaEventRecord(cEv[ch], s2);
    }

    // stream 0: gemm Z,F columns per m-chunk, gated on its conversion
    for (int ch = 0; ch < 4; ch++) {
        cudaStreamWaitEvent(0, cEv[ch], 0);
        gemm_gates<<<dim3(16, MCHUNK / BM), THREADS, SMEM_TOTAL>>>(b, 0, ch * MCHUNK);
    }
    cudaEventRecord(evZF, 0);

    // gemm O columns over full M (stream 0 already waited on all conversion events)
    gemm_gates<<<dim3(8, M_TOT / BM), THREADS, SMEM_TOTAL>>>(b, 16 * BN, 0);

    // s2: scans over Z,F run concurrently with gemm(O)
    cudaStreamWaitEvent(s2, evZF, 0);
    scan_partial<<<SEGS * CH2 / 128, 128, 0, s2>>>();
    scan_combine<<<CH2 / 128, 128, 0, s2>>>(hidden, out + (size_t)M_TOT * DIM);
    cudaEventRecord(evScan, s2);

    // join: scan_final needs O gates (stream 0) + segment states (s2)
    cudaStreamWaitEvent(0, evScan, 0);
    scan_final<<<SEGS * CH2 / 128, 128>>>(out);
}

// round 16
// speedup vs baseline: 1.0377x; 1.0377x over previous
#include <cuda_runtime.h>
#include <cuda_fp16.h>
#include <cstdint>

// ---------------- problem constants ----------------
#define S_LEN 2048
#define BATCH 16
#define DIM   1024
#define M_TOT (S_LEN*BATCH)      // 32768
#define N_TOT (3*DIM)            // 3072
#define K_TOT DIM                // 1024

// GEMM tiling (fp16 operands, fp32 accum) — 2 CTAs/SM, BK=64 (R10 plateau config)
#define BM 128
#define BN 128
#define BK 64
#define KSTEPS (K_TOT/BK)        // 16
#define NSTAGE 3
#define LOOKAHEAD 2
#define THREADS 256
#define SA_BYTES (BM*BK*2)       // 16384 per stage
#define SB_BYTES (BN*BK*2)       // 16384 per stage
#define SMEM_TOTAL (NSTAGE*(SA_BYTES+SB_BYTES))   // 98304 per CTA

// scan partitioning
#define SEGS 64
#define SEGLEN (S_LEN/SEGS)      // 32
#define CH (BATCH*DIM)           // 16384
#define CH2 (CH/2)               // 8192 channel-pairs

// conversion sizes (in float4 units)
#define X4 (M_TOT*K_TOT/4)       // 8388608
#define W4 (N_TOT*K_TOT/4)       // 786432

// ---------------- device scratch ----------------
__device__ __half g_yact[(size_t)M_TOT * N_TOT]; // activated gates (fp16): tanh(Z), sig(F), sig(O)
__device__ __half g_Xh[(size_t)M_TOT * K_TOT];   // fp16-rounded X
__device__ __half g_Wh[(size_t)N_TOT * K_TOT];   // fp16-rounded W
__device__ float g_seg_a[SEGS*CH];
__device__ float g_seg_c[SEGS*CH];
__device__ float g_seg_s[SEGS*CH];

// ---------------- helpers ----------------
__device__ __forceinline__ uint32_t smem_u32(const void* p) {
    uint32_t a;
    asm("{ .reg .u64 t; cvta.to.shared.u64 t, %1; cvt.u32.u64 %0, t; }" : "=r"(a) : "l"(p));
    return a;
}
__device__ __forceinline__ void cp_async16(uint32_t dst, const void* src) {
    asm volatile("cp.async.cg.shared.global [%0], [%1], 16;" :: "r"(dst), "l"(src) : "memory");
}
__device__ __forceinline__ void cp_commit() {
    asm volatile("cp.async.commit_group;" ::: "memory");
}
__device__ __forceinline__ void cp_wait1() {
    asm volatile("cp.async.wait_group 1;" ::: "memory");
}

__device__ __forceinline__ void ldsm_x4(uint32_t* r, uint32_t addr) {
    asm volatile("ldmatrix.sync.aligned.m8n8.x4.shared.b16 {%0,%1,%2,%3}, [%4];"
        : "=r"(r[0]), "=r"(r[1]), "=r"(r[2]), "=r"(r[3]) : "r"(addr));
}

// mma.sync m16n8k16 fp16 in / fp32 accumulate (baseline PTX, sm_80+)
__device__ __forceinline__ void mma_f16(float* d, const uint32_t* a, uint32_t b0, uint32_t b1) {
    asm volatile(
        "mma.sync.aligned.m16n8k16.row.col.f32.f16.f16.f32 "
        "{%0,%1,%2,%3}, {%4,%5,%6,%7}, {%8,%9}, {%0,%1,%2,%3};"
        : "+f"(d[0]), "+f"(d[1]), "+f"(d[2]), "+f"(d[3])
        : "r"(a[0]), "r"(a[1]), "r"(a[2]), "r"(a[3]), "r"(b0), "r"(b1));
}

__device__ __forceinline__ float fsigmoid(float x) { return 1.0f / (1.0f + __expf(-x)); }
__device__ __forceinline__ float ftanh(float x)    { return 2.0f * fsigmoid(2.0f * x) - 1.0f; }

// streaming (evict-first) loads/stores
__device__ __forceinline__ uint32_t ldcs_u32(const uint32_t* p) {
    uint32_t v;
    asm volatile("ld.global.cs.b32 %0, [%1];" : "=r"(v) : "l"(p));
    return v;
}
__device__ __forceinline__ float4 ldcs_f4(const float4* p) {
    float4 v;
    asm volatile("ld.global.cs.v4.f32 {%0,%1,%2,%3}, [%4];"
        : "=f"(v.x), "=f"(v.y), "=f"(v.z), "=f"(v.w) : "l"(p));
    return v;
}
__device__ __forceinline__ void stcs_f2(float* p, float2 v) {
    asm volatile("st.global.cs.v2.f32 [%0], {%1, %2};" :: "l"(p), "f"(v.x), "f"(v.y));
}

// smem swizzle for 128B rows (8 x 16B chunks): chunk ^= row&7
__device__ __forceinline__ uint32_t swz_addr(uint32_t base, int row, int chunk) {
    return base + row * 128 + (((uint32_t)(chunk ^ (row & 7))) << 4);
}

// ============================================================
// Kernel 0: fp32 -> fp16 conversion (2 float4/thread, streaming loads)
// ============================================================
__global__ void __launch_bounds__(256)
to_half_pass(const float* __restrict__ src, __half* __restrict__ dst, int n4) {
    int i = blockIdx.x * 256 + threadIdx.x;
    const int half_n = n4 >> 1;
    #pragma unroll
    for (int r = 0; r < 2; r++) {
        int idx = i + r * half_n;
        if (idx < n4) {
            float4 v = ldcs_f4((const float4*)src + idx);
            __half2 h0 = __float22half2_rn(make_float2(v.x, v.y));
            __half2 h1 = __float22half2_rn(make_float2(v.z, v.w));
            ((uint2*)dst)[idx] = make_uint2(*(uint32_t*)&h0, *(uint32_t*)&h1);
        }
    }
}

// ============================================================
// Kernel 1: Y = act(X @ W^T + b)  via mma.sync fp16 (n_base selects gate range)
//   256 threads (8 warps = 4m x 2n of 32x64 tiles), 2 CTAs/SM
// ============================================================
__global__ void __launch_bounds__(THREADS, 2)
gemm_gates(const float* __restrict__ bias, int n_base) {
    extern __shared__ char smem[];
    const uint32_t sA0 = smem_u32(smem);                    // 3 stages of A
    const uint32_t sB0 = sA0 + NSTAGE * SA_BYTES;           // 3 stages of B

    const int tid  = threadIdx.x;
    const int lane = tid & 31;
    const int wid  = tid >> 5;          // 0..7
    const int wm   = wid & 3;           // 32-row slice
    const int wn   = wid >> 2;          // 64-col slice (0..1)
    const int m0   = blockIdx.y * BM;
    const int nt   = n_base / BN + blockIdx.x;
    const int n0   = nt * BN;
    const int gate = nt >> 3;           // 0=Z(tanh) 1=F(sig) 2=O(sig)

    float acc[2][8][4];
    #pragma unroll
    for (int i = 0; i < 2; i++)
        #pragma unroll
        for (int j = 0; j < 8; j++)
            #pragma unroll
            for (int c = 0; c < 4; c++) acc[i][j][c] = 0.0f;

    // ---- cp.async fill (16B chunks; 8 per 128B row). A: 4/thr, B: 4/thr ----
    auto issue = [&](int kt, int buf) {
        const uint32_t sA = sA0 + buf * SA_BYTES;
        const uint32_t sB = sB0 + buf * SB_BYTES;
        const __half* xb = g_Xh + (size_t)m0 * K_TOT + kt * BK;
        const __half* wb = g_Wh + (size_t)n0 * K_TOT + kt * BK;
        #pragma unroll
        for (int i = 0; i < 4; i++) {
            int id = tid + i * THREADS;
            int r = id >> 3, c = id & 7;
            cp_async16(swz_addr(sA, r, c), xb + (size_t)r * K_TOT + c * 8);
        }
        #pragma unroll
        for (int i = 0; i < 4; i++) {
            int id = tid + i * THREADS;
            int r = id >> 3, c = id & 7;
            cp_async16(swz_addr(sB, r, c), wb + (size_t)r * K_TOT + c * 8);
        }
        cp_commit();
    };

    // ---- per-lane fragment addressing ----
    const int l15 = lane & 15;
    const int lhi = lane >> 4;                 // 0/1 -> k-lo / k-hi 16B chunk of k16 step
    const int aRowBase = wm * 32 + l15;        // + i*16
    const int bRowBase = wn * 64 + l15;        // + jb*16

    issue(0, 0);
    issue(1, 1);

    // fragment double buffers: a 2x2x4, b 2x4x4  (48 regs)
    uint32_t afr[2][2][4], bfr[2][4][4];

    for (int kt = 0; kt < KSTEPS; kt++) {
        cp_wait1();                              // group kt complete
        __syncthreads();                         // also WAR-protects issue below
        const int nb = kt + LOOKAHEAD;
        if (nb < KSTEPS) issue(nb, nb % NSTAGE);
        else             cp_commit();            // keep group count consistent

        const int buf = kt % NSTAGE;
        const uint32_t sA = sA0 + buf * SA_BYTES;
        const uint32_t sB = sB0 + buf * SB_BYTES;

        // prologue: load fragments of ks=0 into buffer 0
        {
            const int chunk = lhi;
            #pragma unroll
            for (int i = 0; i < 2; i++)
                ldsm_x4(afr[0][i], swz_addr(sA, aRowBase + i * 16, chunk));
            #pragma unroll
            for (int jb = 0; jb < 4; jb++)
                ldsm_x4(bfr[0][jb], swz_addr(sB, bRowBase + jb * 16, chunk));
        }

        #pragma unroll
        for (int ks = 0; ks < 4; ks++) {         // four k16 steps per BK=64
            const int cur = ks & 1, nxt = cur ^ 1;
            if (ks < 3) {                        // prefetch ks+1 fragments
                const int chunk = (ks + 1) * 2 + lhi;
                #pragma unroll
                for (int i = 0; i < 2; i++)
                    ldsm_x4(afr[nxt][i], swz_addr(sA, aRowBase + i * 16, chunk));
                #pragma unroll
                for (int jb = 0; jb < 4; jb++)
                    ldsm_x4(bfr[nxt][jb], swz_addr(sB, bRowBase + jb * 16, chunk));
            }
            #pragma unroll
            for (int jb = 0; jb < 4; jb++) {
                #pragma unroll
                for (int i = 0; i < 2; i++) {
                    mma_f16(acc[i][jb * 2 + 0], afr[cur][i], bfr[cur][jb][0], bfr[cur][jb][2]);
                    mma_f16(acc[i][jb * 2 + 1], afr[cur][i], bfr[cur][jb][1], bfr[cur][jb][3]);
                }
            }
        }
        // no trailing barrier: next iteration's wait+sync covers buffer reuse
    }

    // ---- epilogue: bias + activation, fp16 (half2) stores ----
    const int lrow = lane >> 2, lcol = lane & 3;
    #pragma unroll
    for (int j = 0; j < 8; j++) {
        const int n = n0 + wn * 64 + j * 8 + lcol * 2;   // even
        const float b0 = __ldg(bias + n);
        const float b1 = __ldg(bias + n + 1);
        #pragma unroll
        for (int i = 0; i < 2; i++) {
            const int m = m0 + wm * 32 + i * 16 + lrow;
            float y0 = acc[i][j][0] + b0, y1 = acc[i][j][1] + b1;
            float y2 = acc[i][j][2] + b0, y3 = acc[i][j][3] + b1;
            float2 v0, v1;
            if (gate == 0) {
                v0 = make_float2(ftanh(y0), ftanh(y1));
                v1 = make_float2(ftanh(y2), ftanh(y3));
            } else {
                v0 = make_float2(fsigmoid(y0), fsigmoid(y1));
                v1 = make_float2(fsigmoid(y2), fsigmoid(y3));
            }
            *(__half2*)&g_yact[(size_t)m * N_TOT + n]       = __float22half2_rn(v0);
            *(__half2*)&g_yact[(size_t)(m + 8) * N_TOT + n] = __float22half2_rn(v1);
        }
    }
}

// ============================================================
// Kernel 2: per-segment affine reduction, 2 channels/thread (streaming half2 loads)
//   a = prod(1-f), c = local scan from 0   (needs Z,F gates only)
// ============================================================
__global__ void __launch_bounds__(128)
scan_partial() {
    const int g = blockIdx.x * 128 + threadIdx.x;       // seg*CH2 + ch2
    const int seg = g >> 13;                            // /CH2
    const int ch2 = g & (CH2 - 1);
    const int b = ch2 >> 9, d2 = ch2 & 511;
    const uint32_t* Y = (const uint32_t*)g_yact;        // half2 row length N_TOT/2

    float2 a = make_float2(1.0f, 1.0f);
    float2 c = make_float2(0.0f, 0.0f);
    const int t0 = seg * SEGLEN;
    #pragma unroll 4
    for (int t = t0; t < t0 + SEGLEN; t++) {
        size_t rb = (size_t)(t * BATCH + b) * (N_TOT / 2);
        uint32_t zu = ldcs_u32(Y + rb + d2);
        uint32_t fu = ldcs_u32(Y + rb + (DIM / 2) + d2);
        float2 z = __half22float2(*(__half2*)&zu);
        float2 f = __half22float2(*(__half2*)&fu);
        c.x = fmaf(f.x, z.x - c.x, c.x);
        c.y = fmaf(f.y, z.y - c.y, c.y);
        a.x *= (1.0f - f.x);
        a.y *= (1.0f - f.y);
    }
    *(float2*)&g_seg_a[seg * CH + ch2 * 2] = a;
    *(float2*)&g_seg_c[seg * CH + ch2 * 2] = c;
}

// ============================================================
// Kernel 3: sequential combine over 64 segments; emits segment start states + C_last
// ============================================================
__global__ void __launch_bounds__(128)
scan_combine(const float* __restrict__ hidden, float* __restrict__ c_last) {
    const int ch2 = blockIdx.x * 128 + threadIdx.x;     // 0..CH2
    float2 s = *(const float2*)&hidden[ch2 * 2];
    // prefetch segment 0
    float2 aa = *(const float2*)&g_seg_a[ch2 * 2];
    float2 cc = *(const float2*)&g_seg_c[ch2 * 2];
    #pragma unroll
    for (int p = 0; p < SEGS; p++) {
        *(float2*)&g_seg_s[p * CH + ch2 * 2] = s;
        float2 na, nc;
        if (p + 1 < SEGS) {
            na = *(const float2*)&g_seg_a[(p + 1) * CH + ch2 * 2];
            nc = *(const float2*)&g_seg_c[(p + 1) * CH + ch2 * 2];
        }
        s.x = fmaf(aa.x, s.x, cc.x);
        s.y = fmaf(aa.y, s.y, cc.y);
        aa = na; cc = nc;
    }
    *(float2*)&c_last[ch2 * 2] = s;
}

// ============================================================
// Kernel 4: replay segments from start state, write H = sig(O) * C (streaming)
// ============================================================
__global__ void __launch_bounds__(128)
scan_final(float* __restrict__ H) {
    const int g = blockIdx.x * 128 + threadIdx.x;
    const int seg = g >> 13;
    const int ch2 = g & (CH2 - 1);
    const int b = ch2 >> 9, d2 = ch2 & 511;
    const uint32_t* Y = (const uint32_t*)g_yact;

    float2 h = *(const float2*)&g_seg_s[seg * CH + ch2 * 2];
    const int t0 = seg * SEGLEN;
    #pragma unroll 4
    for (int t = t0; t < t0 + SEGLEN; t++) {
        size_t rb = (size_t)(t * BATCH + b) * (N_TOT / 2);
        uint32_t zu = ldcs_u32(Y + rb + d2);
        uint32_t fu = ldcs_u32(Y + rb + (DIM / 2) + d2);
        uint32_t ou = ldcs_u32(Y + rb + DIM + d2);
        float2 z = __half22float2(*(__half2*)&zu);
        float2 f = __half22float2(*(__half2*)&fu);
        float2 o = __half22float2(*(__half2*)&ou);
        h.x = fmaf(f.x, z.x - h.x, h.x);
        h.y = fmaf(f.y, z.y - h.y, h.y);
        stcs_f2(&H[(size_t)(t * BATCH + b) * DIM + d2 * 2],
                make_float2(o.x * h.x, o.y * h.y));
    }
}

// ============================================================
// launcher — R13 structure: unchunked GEMM; W conversion on s2;
//   scans on s2 overlap gemm(O); stream 0 joins for scan_final.
// ============================================================
extern "C" void kernel_launch(void* const* d_in, const int* in_sizes, int n_in,
                              void* d_out, int out_size) {
    const float* X      = (const float*)d_in[0];   // (S,B,D)
    const float* hidden = (const float*)d_in[1];   // (B,D)
    const float* W      = (const float*)d_in[2];   // (3D,D)
    const float* b      = (const float*)d_in[3];   // (3D,)
    float* out = (float*)d_out;                    // H (S,B,D) then C_last (1,B,D)

    static cudaStream_t s2 = nullptr;
    static cudaEvent_t evFork = nullptr, evW = nullptr, evZF = nullptr, evScan = nullptr;
    if (!s2) {
        cudaStreamCreateWithFlags(&s2, cudaStreamNonBlocking);
        cudaEventCreateWithFlags(&evFork, cudaEventDisableTiming);
        cudaEventCreateWithFlags(&evW, cudaEventDisableTiming);
        cudaEventCreateWithFlags(&evZF, cudaEventDisableTiming);
        cudaEventCreateWithFlags(&evScan, cudaEventDisableTiming);
        cudaFuncSetAttribute(gemm_gates, cudaFuncAttributeMaxDynamicSharedMemorySize, SMEM_TOTAL);
    }

    __half* xh; cudaGetSymbolAddress((void**)&xh, g_Xh);
    __half* wh; cudaGetSymbolAddress((void**)&wh, g_Wh);

    // fork s2 from capture-origin stream; convert W there concurrently with X
    cudaEventRecord(evFork, 0);
    cudaStreamWaitEvent(s2, evFork, 0);
    to_half_pass<<<(W4 / 2 + 255) / 256, 256, 0, s2>>>(W, wh, W4);
    cudaEventRecord(evW, s2);

    // stream 0: convert X (bulk of the traffic)
    to_half_pass<<<(X4 / 2 + 255) / 256, 256>>>(X, xh, X4);

    // gemm over Z and F gate columns (nt 0..15) — needs X (stream order) + W (event)
    cudaStreamWaitEvent(0, evW, 0);
    gemm_gates<<<dim3(16, M_TOT / BM), THREADS, SMEM_TOTAL>>>(b, 0);
    cudaEventRecord(evZF, 0);

    // gemm over O gate columns (nt 16..23) continues on stream 0
    gemm_gates<<<dim3(8, M_TOT / BM), THREADS, SMEM_TOTAL>>>(b, 16 * BN);

    // s2: scans over Z,F run concurrently with gemm(O)
    cudaStreamWaitEvent(s2, evZF, 0);
    scan_partial<<<SEGS * CH2 / 128, 128, 0, s2>>>();
    scan_combine<<<CH2 / 128, 128, 0, s2>>>(hidden, out + (size_t)M_TOT * DIM);
    cudaEventRecord(evScan, s2);

    // join: scan_final needs O gates (stream 0) + segment states (s2)
    cudaStreamWaitEvent(0, evScan, 0);
    scan_final<<<SEGS * CH2 / 128, 128>>>(out);
}

// round 17
// speedup vs baseline: 1.0565x; 1.0181x over previous
#include <cuda_runtime.h>
#include <cuda_fp16.h>
#include <cstdint>

// ---------------- problem constants ----------------
#define S_LEN 2048
#define BATCH 16
#define DIM   1024
#define M_TOT (S_LEN*BATCH)      // 32768
#define N_TOT (3*DIM)            // 3072
#define K_TOT DIM                // 1024

// GEMM tiling (fp16 operands, fp32 accum) — 2 CTAs/SM, BK=64
#define BM 128
#define BN 128
#define BK 64
#define KSTEPS (K_TOT/BK)        // 16
#define NSTAGE 3
#define LOOKAHEAD 2
#define THREADS 256
#define SA_BYTES (BM*BK*2)       // 16384 per stage
#define SB_BYTES (BN*BK*2)       // 16384 per stage
#define SMEM_TOTAL (NSTAGE*(SA_BYTES+SB_BYTES))   // 98304 per CTA

// scan partitioning
#define SEGS 64
#define SEGLEN (S_LEN/SEGS)      // 32
#define CH (BATCH*DIM)           // 16384
#define CH2 (CH/2)               // 8192 channel-pairs

// conversion sizes (in float4 units)
#define X4 (M_TOT*K_TOT/4)       // 8388608
#define W4 (N_TOT*K_TOT/4)       // 786432

// ---------------- device scratch ----------------
__device__ __half g_yact[(size_t)M_TOT * N_TOT]; // activated gates (fp16): tanh(Z), sig(F), sig(O)
__device__ __half g_Xh[(size_t)M_TOT * K_TOT];   // fp16-rounded X
__device__ __half g_Wh[(size_t)N_TOT * K_TOT];   // fp16-rounded W
__device__ float g_seg_a[SEGS*CH];
__device__ float g_seg_c[SEGS*CH];
__device__ float g_seg_s[SEGS*CH];

// ---------------- helpers ----------------
__device__ __forceinline__ uint32_t smem_u32(const void* p) {
    uint32_t a;
    asm("{ .reg .u64 t; cvta.to.shared.u64 t, %1; cvt.u32.u64 %0, t; }" : "=r"(a) : "l"(p));
    return a;
}
__device__ __forceinline__ void cp_async16(uint32_t dst, const void* src) {
    asm volatile("cp.async.cg.shared.global [%0], [%1], 16;" :: "r"(dst), "l"(src) : "memory");
}
__device__ __forceinline__ void cp_commit() {
    asm volatile("cp.async.commit_group;" ::: "memory");
}
__device__ __forceinline__ void cp_wait1() {
    asm volatile("cp.async.wait_group 1;" ::: "memory");
}

__device__ __forceinline__ void ldsm_x4(uint32_t* r, uint32_t addr) {
    asm volatile("ldmatrix.sync.aligned.m8n8.x4.shared.b16 {%0,%1,%2,%3}, [%4];"
        : "=r"(r[0]), "=r"(r[1]), "=r"(r[2]), "=r"(r[3]) : "r"(addr));
}

// mma.sync m16n8k16 fp16 in / fp32 accumulate (baseline PTX, sm_80+)
__device__ __forceinline__ void mma_f16(float* d, const uint32_t* a, uint32_t b0, uint32_t b1) {
    asm volatile(
        "mma.sync.aligned.m16n8k16.row.col.f32.f16.f16.f32 "
        "{%0,%1,%2,%3}, {%4,%5,%6,%7}, {%8,%9}, {%0,%1,%2,%3};"
        : "+f"(d[0]), "+f"(d[1]), "+f"(d[2]), "+f"(d[3])
        : "r"(a[0]), "r"(a[1]), "r"(a[2]), "r"(a[3]), "r"(b0), "r"(b1));
}

__device__ __forceinline__ float fsigmoid(float x) { return 1.0f / (1.0f + __expf(-x)); }
__device__ __forceinline__ float ftanh(float x)    { return 2.0f * fsigmoid(2.0f * x) - 1.0f; }

// streaming (evict-first) loads/stores
__device__ __forceinline__ uint32_t ldcs_u32(const uint32_t* p) {
    uint32_t v;
    asm volatile("ld.global.cs.b32 %0, [%1];" : "=r"(v) : "l"(p));
    return v;
}
__device__ __forceinline__ float4 ldcs_f4(const float4* p) {
    float4 v;
    asm volatile("ld.global.cs.v4.f32 {%0,%1,%2,%3}, [%4];"
        : "=f"(v.x), "=f"(v.y), "=f"(v.z), "=f"(v.w) : "l"(p));
    return v;
}
__device__ __forceinline__ void stcs_f2(float* p, float2 v) {
    asm volatile("st.global.cs.v2.f32 [%0], {%1, %2};" :: "l"(p), "f"(v.x), "f"(v.y));
}

// ============================================================
// Kernel 0: fp32 -> fp16 conversion (2 float4/thread, streaming loads)
// ============================================================
__global__ void __launch_bounds__(256)
to_half_pass(const float* __restrict__ src, __half* __restrict__ dst, int n4) {
    int i = blockIdx.x * 256 + threadIdx.x;
    const int half_n = n4 >> 1;
    #pragma unroll
    for (int r = 0; r < 2; r++) {
        int idx = i + r * half_n;
        if (idx < n4) {
            float4 v = ldcs_f4((const float4*)src + idx);
            __half2 h0 = __float22half2_rn(make_float2(v.x, v.y));
            __half2 h1 = __float22half2_rn(make_float2(v.z, v.w));
            ((uint2*)dst)[idx] = make_uint2(*(uint32_t*)&h0, *(uint32_t*)&h1);
        }
    }
}

// ============================================================
// Kernel 1: Y = act(X @ W^T + b)  via mma.sync fp16
//   256 threads (8 warps = 4m x 2n of 32x64 tiles), 2 CTAs/SM
//   All smem addressing precomputed; cp.async spread across ks steps
// ============================================================
__global__ void __launch_bounds__(THREADS, 2)
gemm_gates(const float* __restrict__ bias, int n_base) {
    extern __shared__ char smem[];
    const uint32_t sA0 = smem_u32(smem);                    // 3 stages of A
    const uint32_t sB0 = sA0 + NSTAGE * SA_BYTES;           // 3 stages of B

    const int tid  = threadIdx.x;
    const int lane = tid & 31;
    const int wid  = tid >> 5;          // 0..7
    const int wm   = wid & 3;           // 32-row slice
    const int wn   = wid >> 2;          // 64-col slice (0..1)
    const int m0   = blockIdx.y * BM;
    const int nt   = n_base / BN + blockIdx.x;
    const int n0   = nt * BN;
    const int gate = nt >> 3;           // 0=Z(tanh) 1=F(sig) 2=O(sig)

    float acc[2][8][4];
    #pragma unroll
    for (int i = 0; i < 2; i++)
        #pragma unroll
        for (int j = 0; j < 8; j++)
            #pragma unroll
            for (int c = 0; c < 4; c++) acc[i][j][c] = 0.0f;

    // ---- precomputed cp.async offsets (loop-invariant per thread) ----
    // id_i = tid + i*THREADS; r = id>>3 (row), c = id&7 (16B chunk in 128B row)
    uint32_t cpDst[4];      // swizzled smem offset within a stage
    uint32_t cpSrc[4];      // element offset within the (m0/n0, kt) tile
    #pragma unroll
    for (int i = 0; i < 4; i++) {
        int id = tid + i * THREADS;
        int r = id >> 3, c = id & 7;
        cpDst[i] = (uint32_t)(r * 128) + (((uint32_t)(c ^ (r & 7))) << 4);
        cpSrc[i] = (uint32_t)(r * K_TOT + c * 8);
    }

    // ---- precomputed LDSM addressing ----
    // addr = stageBase + rowOff + kOff[ks]; XOR distributes over <<4
    const int l15 = lane & 15;
    const int lhi = lane >> 4;
    const uint32_t e16 = ((uint32_t)(l15 & 7)) << 4;
    uint32_t kOff[4];
    #pragma unroll
    for (int ks = 0; ks < 4; ks++)
        kOff[ks] = (((uint32_t)(ks * 2 + lhi)) << 4) ^ e16;
    uint32_t aRowOff[2], bRowOff[4];
    #pragma unroll
    for (int i = 0; i < 2; i++) aRowOff[i] = (uint32_t)((wm * 32 + l15 + i * 16) * 128);
    #pragma unroll
    for (int j = 0; j < 4; j++) bRowOff[j] = (uint32_t)((wn * 64 + l15 + j * 16) * 128);

    const __half* xbase = g_Xh + (size_t)m0 * K_TOT;
    const __half* wbase = g_Wh + (size_t)n0 * K_TOT;

    // prologue: fill stages 0 and 1
    #pragma unroll
    for (int kt = 0; kt < 2; kt++) {
        const uint32_t sA = sA0 + kt * SA_BYTES;
        const uint32_t sB = sB0 + kt * SB_BYTES;
        const __half* xb = xbase + kt * BK;
        const __half* wb = wbase + kt * BK;
        #pragma unroll
        for (int i = 0; i < 4; i++) {
            cp_async16(sA + cpDst[i], xb + cpSrc[i]);
            cp_async16(sB + cpDst[i], wb + cpSrc[i]);
        }
        cp_commit();
    }

    for (int kt = 0; kt < KSTEPS; kt++) {
        cp_wait1();                              // group kt complete
        __syncthreads();                         // WAR-protects the fills below

        const int buf = kt % NSTAGE;
        const uint32_t sAb = sA0 + buf * SA_BYTES;
        const uint32_t sBb = sB0 + buf * SB_BYTES;
        uint32_t aS[2], bS[4];
        #pragma unroll
        for (int i = 0; i < 2; i++) aS[i] = sAb + aRowOff[i];
        #pragma unroll
        for (int j = 0; j < 4; j++) bS[j] = sBb + bRowOff[j];

        // next-fill targets (spread across ks steps)
        const int nb = kt + LOOKAHEAD;
        const bool doFill = (nb < KSTEPS);
        const int nbuf = nb % NSTAGE;
        const uint32_t nsA = sA0 + nbuf * SA_BYTES;
        const uint32_t nsB = sB0 + nbuf * SB_BYTES;
        const __half* xb_n = xbase + nb * BK;
        const __half* wb_n = wbase + nb * BK;

        #pragma unroll
        for (int ks = 0; ks < 4; ks++) {         // four k16 steps per BK=64
            uint32_t a[2][4], r[4];
            #pragma unroll
            for (int i = 0; i < 2; i++)
                ldsm_x4(a[i], aS[i] + kOff[ks]);

            // interleave 2 cp.asyncs per ks step (A halves at ks 0-1, B at ks 2-3)
            if (doFill) {
                if (ks < 2) {
                    #pragma unroll
                    for (int i = 0; i < 2; i++) {
                        int q = ks * 2 + i;
                        cp_async16(nsA + cpDst[q], xb_n + cpSrc[q]);
                    }
                } else {
                    #pragma unroll
                    for (int i = 0; i < 2; i++) {
                        int q = (ks - 2) * 2 + i;
                        cp_async16(nsB + cpDst[q], wb_n + cpSrc[q]);
                    }
                }
            }
            if (ks == 3) cp_commit();            // one group per k-tile (possibly empty)

            #pragma unroll
            for (int jb = 0; jb < 4; jb++) {
                ldsm_x4(r, bS[jb] + kOff[ks]);
                #pragma unroll
                for (int i = 0; i < 2; i++) {
                    mma_f16(acc[i][jb * 2 + 0], a[i], r[0], r[2]);
                    mma_f16(acc[i][jb * 2 + 1], a[i], r[1], r[3]);
                }
            }
        }
        // no trailing barrier: next iteration's wait+sync covers buffer reuse
    }

    // ---- epilogue: bias + activation, fp16 (half2) stores ----
    const int lrow = lane >> 2, lcol = lane & 3;
    #pragma unroll
    for (int j = 0; j < 8; j++) {
        const int n = n0 + wn * 64 + j * 8 + lcol * 2;   // even
        const float b0 = __ldg(bias + n);
        const float b1 = __ldg(bias + n + 1);
        #pragma unroll
        for (int i = 0; i < 2; i++) {
            const int m = m0 + wm * 32 + i * 16 + lrow;
            float y0 = acc[i][j][0] + b0, y1 = acc[i][j][1] + b1;
            float y2 = acc[i][j][2] + b0, y3 = acc[i][j][3] + b1;
            float2 v0, v1;
            if (gate == 0) {
                v0 = make_float2(ftanh(y0), ftanh(y1));
                v1 = make_float2(ftanh(y2), ftanh(y3));
            } else {
                v0 = make_float2(fsigmoid(y0), fsigmoid(y1));
                v1 = make_float2(fsigmoid(y2), fsigmoid(y3));
            }
            *(__half2*)&g_yact[(size_t)m * N_TOT + n]       = __float22half2_rn(v0);
            *(__half2*)&g_yact[(size_t)(m + 8) * N_TOT + n] = __float22half2_rn(v1);
        }
    }
}

// ============================================================
// Kernel 2: per-segment affine reduction, 2 channels/thread (streaming half2 loads)
//   a = prod(1-f), c = local scan from 0   (needs Z,F gates only)
// ============================================================
__global__ void __launch_bounds__(128)
scan_partial() {
    const int g = blockIdx.x * 128 + threadIdx.x;       // seg*CH2 + ch2
    const int seg = g >> 13;                            // /CH2
    const int ch2 = g & (CH2 - 1);
    const int b = ch2 >> 9, d2 = ch2 & 511;
    const uint32_t* Y = (const uint32_t*)g_yact;        // half2 row length N_TOT/2

    float2 a = make_float2(1.0f, 1.0f);
    float2 c = make_float2(0.0f, 0.0f);
    const int t0 = seg * SEGLEN;
    #pragma unroll 4
    for (int t = t0; t < t0 + SEGLEN; t++) {
        size_t rb = (size_t)(t * BATCH + b) * (N_TOT / 2);
        uint32_t zu = ldcs_u32(Y + rb + d2);
        uint32_t fu = ldcs_u32(Y + rb + (DIM / 2) + d2);
        float2 z = __half22float2(*(__half2*)&zu);
        float2 f = __half22float2(*(__half2*)&fu);
        c.x = fmaf(f.x, z.x - c.x, c.x);
        c.y = fmaf(f.y, z.y - c.y, c.y);
        a.x *= (1.0f - f.x);
        a.y *= (1.0f - f.y);
    }
    *(float2*)&g_seg_a[seg * CH + ch2 * 2] = a;
    *(float2*)&g_seg_c[seg * CH + ch2 * 2] = c;
}

// ============================================================
// Kernel 3: sequential combine over 64 segments; emits segment start states + C_last
// ============================================================
__global__ void __launch_bounds__(128)
scan_combine(const float* __restrict__ hidden, float* __restrict__ c_last) {
    const int ch2 = blockIdx.x * 128 + threadIdx.x;     // 0..CH2
    float2 s = *(const float2*)&hidden[ch2 * 2];
    // prefetch segment 0
    float2 aa = *(const float2*)&g_seg_a[ch2 * 2];
    float2 cc = *(const float2*)&g_seg_c[ch2 * 2];
    #pragma unroll
    for (int p = 0; p < SEGS; p++) {
        *(float2*)&g_seg_s[p * CH + ch2 * 2] = s;
        float2 na, nc;
        if (p + 1 < SEGS) {
            na = *(const float2*)&g_seg_a[(p + 1) * CH + ch2 * 2];
            nc = *(const float2*)&g_seg_c[(p + 1) * CH + ch2 * 2];
        }
        s.x = fmaf(aa.x, s.x, cc.x);
        s.y = fmaf(aa.y, s.y, cc.y);
        aa = na; cc = nc;
    }
    *(float2*)&c_last[ch2 * 2] = s;
}

// ============================================================
// Kernel 4: replay segments from start state, write H = sig(O) * C (streaming)
// ============================================================
__global__ void __launch_bounds__(128)
scan_final(float* __restrict__ H) {
    const int g = blockIdx.x * 128 + threadIdx.x;
    const int seg = g >> 13;
    const int ch2 = g & (CH2 - 1);
    const int b = ch2 >> 9, d2 = ch2 & 511;
    const uint32_t* Y = (const uint32_t*)g_yact;

    float2 h = *(const float2*)&g_seg_s[seg * CH + ch2 * 2];
    const int t0 = seg * SEGLEN;
    #pragma unroll 4
    for (int t = t0; t < t0 + SEGLEN; t++) {
        size_t rb = (size_t)(t * BATCH + b) * (N_TOT / 2);
        uint32_t zu = ldcs_u32(Y + rb + d2);
        uint32_t fu = ldcs_u32(Y + rb + (DIM / 2) + d2);
        uint32_t ou = ldcs_u32(Y + rb + DIM + d2);
        float2 z = __half22float2(*(__half2*)&zu);
        float2 f = __half22float2(*(__half2*)&fu);
        float2 o = __half22float2(*(__half2*)&ou);
        h.x = fmaf(f.x, z.x - h.x, h.x);
        h.y = fmaf(f.y, z.y - h.y, h.y);
        stcs_f2(&H[(size_t)(t * BATCH + b) * DIM + d2 * 2],
                make_float2(o.x * h.x, o.y * h.y));
    }
}

// ============================================================
// launcher — R16 structure: unchunked GEMM; W conversion on s2;
//   scans on s2 overlap gemm(O); stream 0 joins for scan_final.
// ============================================================
extern "C" void kernel_launch(void* const* d_in, const int* in_sizes, int n_in,
                              void* d_out, int out_size) {
    const float* X      = (const float*)d_in[0];   // (S,B,D)
    const float* hidden = (const float*)d_in[1];   // (B,D)
    const float* W      = (const float*)d_in[2];   // (3D,D)
    const float* b      = (const float*)d_in[3];   // (3D,)
    float* out = (float*)d_out;                    // H (S,B,D) then C_last (1,B,D)

    static cudaStream_t s2 = nullptr;
    static cudaEvent_t evFork = nullptr, evW = nullptr, evZF = nullptr, evScan = nullptr;
    if (!s2) {
        cudaStreamCreateWithFlags(&s2, cudaStreamNonBlocking);
        cudaEventCreateWithFlags(&evFork, cudaEventDisableTiming);
        cudaEventCreateWithFlags(&evW, cudaEventDisableTiming);
        cudaEventCreateWithFlags(&evZF, cudaEventDisableTiming);
        cudaEventCreateWithFlags(&evScan, cudaEventDisableTiming);
        cudaFuncSetAttribute(gemm_gates, cudaFuncAttributeMaxDynamicSharedMemorySize, SMEM_TOTAL);
    }

    __half* xh; cudaGetSymbolAddress((void**)&xh, g_Xh);
    __half* wh; cudaGetSymbolAddress((void**)&wh, g_Wh);

    // fork s2 from capture-origin stream; convert W there concurrently with X
    cudaEventRecord(evFork, 0);
    cudaStreamWaitEvent(s2, evFork, 0);
    to_half_pass<<<(W4 / 2 + 255) / 256, 256, 0, s2>>>(W, wh, W4);
    cudaEventRecord(evW, s2);

    // stream 0: convert X (bulk of the traffic)
    to_half_pass<<<(X4 / 2 + 255) / 256, 256>>>(X, xh, X4);

    // gemm over Z and F gate columns (nt 0..15) — needs X (stream order) + W (event)
    cudaStreamWaitEvent(0, evW, 0);
    gemm_gates<<<dim3(16, M_TOT / BM), THREADS, SMEM_TOTAL>>>(b, 0);
    cudaEventRecord(evZF, 0);

    // gemm over O gate columns (nt 16..23) continues on stream 0
    gemm_gates<<<dim3(8, M_TOT / BM), THREADS, SMEM_TOTAL>>>(b, 16 * BN);

    // s2: scans over Z,F run concurrently with gemm(O)
    cudaStreamWaitEvent(s2, evZF, 0);
    scan_partial<<<SEGS * CH2 / 128, 128, 0, s2>>>();
    scan_combine<<<CH2 / 128, 128, 0, s2>>>(hidden, out + (size_t)M_TOT * DIM);
    cudaEventRecord(evScan, s2);

    // join: scan_final needs O gates (stream 0) + segment states (s2)
    cudaStreamWaitEvent(0, evScan, 0);
    scan_final<<<SEGS * CH2 / 128, 128>>>(out);
}